// round 8
// baseline (speedup 1.0000x reference)
#include <cuda_runtime.h>
#include <cuda_bf16.h>
#include <cstdint>

#define N_NODES 50000
#define F_IN    128
#define HID     256
#define OUT_F   32
#define E_MAX   2097152

#define NEG_INF (-__builtin_huge_valf())

// ---------------- device scratch (no allocation allowed) ----------------
__device__ float g_h  [(size_t)N_NODES * HID];   // hidden layer [N,256] fp32 (exact, for gather2)
__device__ float g_z  [(size_t)N_NODES * OUT_F]; // output embeddings [N,32]

// bf16 split operands, layer1: A1 = [agg1 | x]  [N,256]
__device__ __nv_bfloat16 g_A1hi[(size_t)N_NODES * 256];
__device__ __nv_bfloat16 g_A1lo[(size_t)N_NODES * 256];
__device__ __nv_bfloat16 g_W1hi[256 * 256];   // [W1l ; W1r]
__device__ __nv_bfloat16 g_W1lo[256 * 256];
// layer2: A2 = [agg2 | h]  [N,512]
__device__ __nv_bfloat16 g_A2hi[(size_t)N_NODES * 512];
__device__ __nv_bfloat16 g_A2lo[(size_t)N_NODES * 512];
__device__ __nv_bfloat16 g_W2hi[512 * OUT_F]; // [W2l ; W2r]
__device__ __nv_bfloat16 g_W2lo[512 * OUT_F];

// CSR scratch. NOTE: g_deg is zeroed at module load and re-zeroed at the END
// of every kernel_launch (deterministic invariant), so hist can run first.
__device__ int g_deg [N_NODES];
__device__ int g_row [N_NODES];
__device__ int g_cur [N_NODES];
__device__ int g_adj [E_MAX];

__device__ __forceinline__ void split_bf16(float v, __nv_bfloat16& hi, __nv_bfloat16& lo) {
    hi = __float2bfloat16_rn(v);
    lo = __float2bfloat16_rn(v - __bfloat162float(hi));
}

// ---------------- CSR build ----------------

__global__ void zero_deg_kernel() {
    int i = blockIdx.x * blockDim.x + threadIdx.x;
    if (i < N_NODES) g_deg[i] = 0;
}

__global__ void hist_kernel(const int* __restrict__ dst, int E) {
    int i = blockIdx.x * blockDim.x + threadIdx.x;
    if (i < E) atomicAdd(&g_deg[dst[i]], 1);
}

// single-block exclusive scan over g_deg -> g_row, g_cur
__global__ void scan_single_kernel() {
    __shared__ int s[1024];
    int tid = threadIdx.x;
    const int CH = (N_NODES + 1023) / 1024;   // 49
    int beg = tid * CH;
    int end = beg + CH; if (end > N_NODES) end = N_NODES;
    int sum = 0;
    for (int i = beg; i < end; i++) sum += g_deg[i];
    s[tid] = sum;
    __syncthreads();
    for (int o = 1; o < 1024; o <<= 1) {
        int t = (tid >= o) ? s[tid - o] : 0;
        __syncthreads();
        s[tid] += t;
        __syncthreads();
    }
    int run = s[tid] - sum;   // exclusive prefix of this chunk
    for (int i = beg; i < end; i++) {
        int d = g_deg[i];
        g_row[i] = run;
        g_cur[i] = run;
        run += d;
    }
}

__global__ void fill_adj_kernel(const int* __restrict__ src,
                                const int* __restrict__ dst, int E) {
    int i = blockIdx.x * blockDim.x + threadIdx.x;
    if (i < E) {
        int p = atomicAdd(&g_cur[dst[i]], 1);
        g_adj[p] = src[i];
    }
}

// ---------------- gathers ----------------

__device__ __forceinline__ float4 max4(float4 a, float4 b) {
    a.x = fmaxf(a.x, b.x); a.y = fmaxf(a.y, b.y);
    a.z = fmaxf(a.z, b.z); a.w = fmaxf(a.w, b.w);
    return a;
}

__device__ __forceinline__ void store_split4(__nv_bfloat16* hi_base, __nv_bfloat16* lo_base,
                                             float4 a) {
    __nv_bfloat16 hx, lx, hy, ly, hz, lz, hw, lw;
    split_bf16(a.x, hx, lx); split_bf16(a.y, hy, ly);
    split_bf16(a.z, hz, lz); split_bf16(a.w, hw, lw);
    ((__nv_bfloat162*)hi_base)[0] = __halves2bfloat162(hx, hy);
    ((__nv_bfloat162*)hi_base)[1] = __halves2bfloat162(hz, hw);
    ((__nv_bfloat162*)lo_base)[0] = __halves2bfloat162(lx, ly);
    ((__nv_bfloat162*)lo_base)[1] = __halves2bfloat162(lz, lw);
}

// Layer 1: one warp per node over x [N,128]; writes agg1 -> A1 cols 0..127 bf16 hi/lo.
__global__ void gather1_kernel(const float* __restrict__ x) {
    int gw = (blockIdx.x * blockDim.x + threadIdx.x) >> 5;
    if (gw >= N_NODES) return;
    int lane = threadIdx.x & 31;

    int start = g_row[gw];
    int deg   = g_deg[gw];

    float4 acc = make_float4(NEG_INF, NEG_INF, NEG_INF, NEG_INF);
    int i = 0;
    for (; i + 8 <= deg; i += 8) {
        int s0 = g_adj[start + i + 0];
        int s1 = g_adj[start + i + 1];
        int s2 = g_adj[start + i + 2];
        int s3 = g_adj[start + i + 3];
        int s4 = g_adj[start + i + 4];
        int s5 = g_adj[start + i + 5];
        int s6 = g_adj[start + i + 6];
        int s7 = g_adj[start + i + 7];
        float4 v0 = ((const float4*)x)[(size_t)s0 * 32 + lane];
        float4 v1 = ((const float4*)x)[(size_t)s1 * 32 + lane];
        float4 v2 = ((const float4*)x)[(size_t)s2 * 32 + lane];
        float4 v3 = ((const float4*)x)[(size_t)s3 * 32 + lane];
        float4 v4 = ((const float4*)x)[(size_t)s4 * 32 + lane];
        float4 v5 = ((const float4*)x)[(size_t)s5 * 32 + lane];
        float4 v6 = ((const float4*)x)[(size_t)s6 * 32 + lane];
        float4 v7 = ((const float4*)x)[(size_t)s7 * 32 + lane];
        float4 m01 = max4(v0, v1), m23 = max4(v2, v3);
        float4 m45 = max4(v4, v5), m67 = max4(v6, v7);
        acc = max4(acc, max4(max4(m01, m23), max4(m45, m67)));
    }
    for (; i < deg; i++) {
        int s0 = g_adj[start + i];
        acc = max4(acc, ((const float4*)x)[(size_t)s0 * 32 + lane]);
    }
    acc.x = (acc.x == NEG_INF) ? 0.0f : acc.x;
    acc.y = (acc.y == NEG_INF) ? 0.0f : acc.y;
    acc.z = (acc.z == NEG_INF) ? 0.0f : acc.z;
    acc.w = (acc.w == NEG_INF) ? 0.0f : acc.w;

    size_t base = (size_t)gw * 256 + lane * 4;
    store_split4(g_A1hi + base, g_A1lo + base, acc);
}

// Layer 2: two warps per node over g_h [N,256] fp32; writes agg2 -> A2 cols 0..255 bf16 hi/lo.
__global__ void gather2_kernel() {
    int gw = (blockIdx.x * blockDim.x + threadIdx.x) >> 5;
    int node = gw >> 1;
    if (node >= N_NODES) return;
    int half = gw & 1;
    int lane = threadIdx.x & 31;
    int q = half * 32 + lane;   // float4 index within 64-wide row

    int start = g_row[node];
    int deg   = g_deg[node];

    const float4* feat = (const float4*)g_h;
    float4 acc = make_float4(NEG_INF, NEG_INF, NEG_INF, NEG_INF);
    int i = 0;
    for (; i + 8 <= deg; i += 8) {
        int s0 = g_adj[start + i + 0];
        int s1 = g_adj[start + i + 1];
        int s2 = g_adj[start + i + 2];
        int s3 = g_adj[start + i + 3];
        int s4 = g_adj[start + i + 4];
        int s5 = g_adj[start + i + 5];
        int s6 = g_adj[start + i + 6];
        int s7 = g_adj[start + i + 7];
        float4 v0 = feat[(size_t)s0 * 64 + q];
        float4 v1 = feat[(size_t)s1 * 64 + q];
        float4 v2 = feat[(size_t)s2 * 64 + q];
        float4 v3 = feat[(size_t)s3 * 64 + q];
        float4 v4 = feat[(size_t)s4 * 64 + q];
        float4 v5 = feat[(size_t)s5 * 64 + q];
        float4 v6 = feat[(size_t)s6 * 64 + q];
        float4 v7 = feat[(size_t)s7 * 64 + q];
        float4 m01 = max4(v0, v1), m23 = max4(v2, v3);
        float4 m45 = max4(v4, v5), m67 = max4(v6, v7);
        acc = max4(acc, max4(max4(m01, m23), max4(m45, m67)));
    }
    for (; i < deg; i++) {
        int s0 = g_adj[start + i];
        acc = max4(acc, feat[(size_t)s0 * 64 + q]);
    }
    acc.x = (acc.x == NEG_INF) ? 0.0f : acc.x;
    acc.y = (acc.y == NEG_INF) ? 0.0f : acc.y;
    acc.z = (acc.z == NEG_INF) ? 0.0f : acc.z;
    acc.w = (acc.w == NEG_INF) ? 0.0f : acc.w;

    size_t base = (size_t)node * 512 + q * 4;
    store_split4(g_A2hi + base, g_A2lo + base, acc);
}

// ---------------- bf16 split prep ----------------

// x [N,128] -> A1 cols 128..255 (hi/lo)
__global__ void convert_x_kernel(const float* __restrict__ x) {
    int t = blockIdx.x * blockDim.x + threadIdx.x;
    if (t >= N_NODES * 32) return;
    int node = t >> 5, q = t & 31;
    float4 v = ((const float4*)x)[(size_t)node * 32 + q];
    size_t base = (size_t)node * 256 + 128 + q * 4;
    store_split4(g_A1hi + base, g_A1lo + base, v);
}

// W1 = [W1l ; W1r] -> hi/lo, [256][256]
__global__ void convert_w1_kernel(const float* __restrict__ W1l,
                                  const float* __restrict__ W1r) {
    int t = blockIdx.x * blockDim.x + threadIdx.x;
    if (t >= 256 * 256) return;
    int k = t >> 8, n = t & 255;
    float v = (k < 128) ? W1l[k * 256 + n] : W1r[(k - 128) * 256 + n];
    split_bf16(v, g_W1hi[t], g_W1lo[t]);
}

// W2 = [W2l ; W2r] -> hi/lo, [512][32]
__global__ void convert_w2_kernel(const float* __restrict__ W2l,
                                  const float* __restrict__ W2r) {
    int t = blockIdx.x * blockDim.x + threadIdx.x;
    if (t >= 512 * OUT_F) return;
    int k = t >> 5, n = t & 31;
    float v = (k < 256) ? W2l[k * OUT_F + n] : W2r[(k - 256) * OUT_F + n];
    split_bf16(v, g_W2hi[t], g_W2lo[t]);
}

// ---------------- tensor-core mma helpers ----------------

#define SA_STRIDE 24   // 16 + 8 pad

__device__ __forceinline__ void ldmat4(uint32_t addr, uint32_t& r0, uint32_t& r1,
                                       uint32_t& r2, uint32_t& r3) {
    asm volatile("ldmatrix.sync.aligned.m8n8.x4.shared.b16 {%0,%1,%2,%3}, [%4];"
                 : "=r"(r0), "=r"(r1), "=r"(r2), "=r"(r3) : "r"(addr));
}

__device__ __forceinline__ void mma16816(float* d, uint32_t a0, uint32_t a1,
                                         uint32_t a2, uint32_t a3,
                                         uint32_t b0, uint32_t b1) {
    asm volatile(
        "mma.sync.aligned.m16n8k16.row.col.f32.bf16.bf16.f32 "
        "{%0,%1,%2,%3},{%4,%5,%6,%7},{%8,%9},{%0,%1,%2,%3};"
        : "+f"(d[0]), "+f"(d[1]), "+f"(d[2]), "+f"(d[3])
        : "r"(a0), "r"(a1), "r"(a2), "r"(a3), "r"(b0), "r"(b1));
}

// ---------------- gemm1: h = relu(A1 @ W1 + b1), also emits h bf16 hi/lo into A2 ----------------

__global__ void __launch_bounds__(512, 1)
gemm1_mma_kernel(const float* __restrict__ bias) {
    __shared__ __nv_bfloat16 sAhi[128][SA_STRIDE];
    __shared__ __nv_bfloat16 sAlo[128][SA_STRIDE];
    __shared__ __nv_bfloat16 sBhi[128][SA_STRIDE];   // B^T: rows = n, cols = k
    __shared__ __nv_bfloat16 sBlo[128][SA_STRIDE];

    int tid = threadIdx.x;
    int m0 = blockIdx.x * 128;
    int n0 = blockIdx.y * 128;

    int warp = tid >> 5, lane = tid & 31;
    int wm = warp & 3, wn = warp >> 2;
    int m_off = wm * 32, n_off = wn * 32;

    int a_buf  = tid >> 8;
    int a_row  = (tid & 255) >> 1;
    int a_half = tid & 1;
    int b_buf  = tid >> 8;
    int b_kk   = (tid & 255) >> 4;
    int b_n8   = (tid & 15) * 8;
    bool a_ok = (m0 + a_row) < N_NODES;

    const __nv_bfloat16* Aglob = a_buf ? g_A1lo : g_A1hi;
    const __nv_bfloat16* Bglob = b_buf ? g_W1lo : g_W1hi;

    float acc[2][4][4];
#pragma unroll
    for (int i = 0; i < 2; i++)
#pragma unroll
        for (int j = 0; j < 4; j++)
#pragma unroll
            for (int q = 0; q < 4; q++) acc[i][j][q] = 0.0f;

    uint4 pa = make_uint4(0, 0, 0, 0), pb;
    if (a_ok) pa = *(const uint4*)(Aglob + (size_t)(m0 + a_row) * 256 + a_half * 8);
    pb = *(const uint4*)(Bglob + (size_t)b_kk * 256 + n0 + b_n8);

    for (int ks = 0; ks < 16; ks++) {
        {
            __nv_bfloat16* sa = a_buf ? &sAlo[a_row][a_half * 8] : &sAhi[a_row][a_half * 8];
            *(uint4*)sa = pa;
            const __nv_bfloat16* w = (const __nv_bfloat16*)&pb;
            __nv_bfloat16 (*sb)[SA_STRIDE] = b_buf ? sBlo : sBhi;
#pragma unroll
            for (int j = 0; j < 8; j++) sb[b_n8 + j][b_kk] = w[j];
        }
        __syncthreads();

        if (ks + 1 < 16) {
            int kbase = (ks + 1) * 16;
            pa = make_uint4(0, 0, 0, 0);
            if (a_ok) pa = *(const uint4*)(Aglob + (size_t)(m0 + a_row) * 256 + kbase + a_half * 8);
            pb = *(const uint4*)(Bglob + (size_t)(kbase + b_kk) * 256 + n0 + b_n8);
        }

        uint32_t ahi[2][4], alo[2][4];
#pragma unroll
        for (int ms = 0; ms < 2; ms++) {
            int r = m_off + ms * 16 + (lane & 15);
            int c = (lane >> 4) * 8;
            ldmat4((uint32_t)__cvta_generic_to_shared(&sAhi[r][c]),
                   ahi[ms][0], ahi[ms][1], ahi[ms][2], ahi[ms][3]);
            ldmat4((uint32_t)__cvta_generic_to_shared(&sAlo[r][c]),
                   alo[ms][0], alo[ms][1], alo[ms][2], alo[ms][3]);
        }
        uint32_t bhi[4][2], blo[4][2];
#pragma unroll
        for (int np = 0; np < 2; np++) {
            int r = n_off + np * 16 + (lane & 15);
            int c = (lane >> 4) * 8;
            uint32_t r0, r1, r2, r3;
            ldmat4((uint32_t)__cvta_generic_to_shared(&sBhi[r][c]), r0, r1, r2, r3);
            bhi[np * 2 + 0][0] = r0; bhi[np * 2 + 0][1] = r2;
            bhi[np * 2 + 1][0] = r1; bhi[np * 2 + 1][1] = r3;
            ldmat4((uint32_t)__cvta_generic_to_shared(&sBlo[r][c]), r0, r1, r2, r3);
            blo[np * 2 + 0][0] = r0; blo[np * 2 + 0][1] = r2;
            blo[np * 2 + 1][0] = r1; blo[np * 2 + 1][1] = r3;
        }

#pragma unroll
        for (int ms = 0; ms < 2; ms++)
#pragma unroll
            for (int ns = 0; ns < 4; ns++) {
                mma16816(acc[ms][ns], ahi[ms][0], ahi[ms][1], ahi[ms][2], ahi[ms][3],
                         bhi[ns][0], bhi[ns][1]);
                mma16816(acc[ms][ns], ahi[ms][0], ahi[ms][1], ahi[ms][2], ahi[ms][3],
                         blo[ns][0], blo[ns][1]);
                mma16816(acc[ms][ns], alo[ms][0], alo[ms][1], alo[ms][2], alo[ms][3],
                         bhi[ns][0], bhi[ns][1]);
            }
        __syncthreads();
    }

    int gid = lane >> 2, tig = lane & 3;
#pragma unroll
    for (int ms = 0; ms < 2; ms++) {
#pragma unroll
        for (int ns = 0; ns < 4; ns++) {
            int gc = n0 + n_off + ns * 8 + tig * 2;
            float b0 = bias[gc], b1v = bias[gc + 1];
            int r0 = m0 + m_off + ms * 16 + gid;
            int r1 = r0 + 8;
#pragma unroll
            for (int rr = 0; rr < 2; rr++) {
                int r = rr ? r1 : r0;
                if (r >= N_NODES) continue;
                float ox = fmaxf(acc[ms][ns][rr * 2 + 0] + b0, 0.0f);
                float oy = fmaxf(acc[ms][ns][rr * 2 + 1] + b1v, 0.0f);
                float2 o; o.x = ox; o.y = oy;
                *(float2*)(g_h + (size_t)r * 256 + gc) = o;
                __nv_bfloat16 hx, lx, hy, ly;
                split_bf16(ox, hx, lx); split_bf16(oy, hy, ly);
                *(__nv_bfloat162*)(g_A2hi + (size_t)r * 512 + 256 + gc) = __halves2bfloat162(hx, hy);
                *(__nv_bfloat162*)(g_A2lo + (size_t)r * 512 + 256 + gc) = __halves2bfloat162(lx, ly);
            }
        }
    }
}

// ---------------- gemm2: z = A2 @ W2 + b2 ----------------

__global__ void __launch_bounds__(256, 1)
gemm2_mma_kernel(const float* __restrict__ bias) {
    __shared__ __nv_bfloat16 sAhi[128][SA_STRIDE];
    __shared__ __nv_bfloat16 sAlo[128][SA_STRIDE];
    __shared__ __nv_bfloat16 sBhi[32][SA_STRIDE];
    __shared__ __nv_bfloat16 sBlo[32][SA_STRIDE];

    int tid = threadIdx.x;
    int m0 = blockIdx.x * 128;
    int warp = tid >> 5, lane = tid & 31;
    int m_off = warp * 16;

    int a_row = tid & 127, a_buf = tid >> 7;
    bool a_ok = (m0 + a_row) < N_NODES;
    const __nv_bfloat16* Aglob = a_buf ? g_A2lo : g_A2hi;
    int b_buf = (tid >> 6) & 1;
    int b_kk  = (tid & 63) >> 2;
    int b_n8  = (tid & 3) * 8;
    bool b_act = tid < 128;
    const __nv_bfloat16* Bglob = b_buf ? g_W2lo : g_W2hi;

    float acc[4][4];
#pragma unroll
    for (int j = 0; j < 4; j++)
#pragma unroll
        for (int q = 0; q < 4; q++) acc[j][q] = 0.0f;

    uint4 pa0 = make_uint4(0,0,0,0), pa1 = pa0, pb = pa0;
    if (a_ok) {
        pa0 = *(const uint4*)(Aglob + (size_t)(m0 + a_row) * 512);
        pa1 = *(const uint4*)(Aglob + (size_t)(m0 + a_row) * 512 + 8);
    }
    if (b_act) pb = *(const uint4*)(Bglob + (size_t)b_kk * OUT_F + b_n8);

    for (int ks = 0; ks < 32; ks++) {
        {
            __nv_bfloat16 (*sa)[SA_STRIDE] = a_buf ? sAlo : sAhi;
            *(uint4*)&sa[a_row][0] = pa0;
            *(uint4*)&sa[a_row][8] = pa1;
            if (b_act) {
                const __nv_bfloat16* w = (const __nv_bfloat16*)&pb;
                __nv_bfloat16 (*sb)[SA_STRIDE] = b_buf ? sBlo : sBhi;
#pragma unroll
                for (int j = 0; j < 8; j++) sb[b_n8 + j][b_kk] = w[j];
            }
        }
        __syncthreads();

        if (ks + 1 < 32) {
            int kbase = (ks + 1) * 16;
            pa0 = make_uint4(0,0,0,0); pa1 = pa0;
            if (a_ok) {
                pa0 = *(const uint4*)(Aglob + (size_t)(m0 + a_row) * 512 + kbase);
                pa1 = *(const uint4*)(Aglob + (size_t)(m0 + a_row) * 512 + kbase + 8);
            }
            if (b_act) pb = *(const uint4*)(Bglob + (size_t)(kbase + b_kk) * OUT_F + b_n8);
        }

        uint32_t ahi[4], alo[4];
        {
            int r = m_off + (lane & 15);
            int c = (lane >> 4) * 8;
            ldmat4((uint32_t)__cvta_generic_to_shared(&sAhi[r][c]), ahi[0], ahi[1], ahi[2], ahi[3]);
            ldmat4((uint32_t)__cvta_generic_to_shared(&sAlo[r][c]), alo[0], alo[1], alo[2], alo[3]);
        }
        uint32_t bhi[4][2], blo[4][2];
#pragma unroll
        for (int np = 0; np < 2; np++) {
            int r = np * 16 + (lane & 15);
            int c = (lane >> 4) * 8;
            uint32_t r0, r1, r2, r3;
            ldmat4((uint32_t)__cvta_generic_to_shared(&sBhi[r][c]), r0, r1, r2, r3);
            bhi[np * 2 + 0][0] = r0; bhi[np * 2 + 0][1] = r2;
            bhi[np * 2 + 1][0] = r1; bhi[np * 2 + 1][1] = r3;
            ldmat4((uint32_t)__cvta_generic_to_shared(&sBlo[r][c]), r0, r1, r2, r3);
            blo[np * 2 + 0][0] = r0; blo[np * 2 + 0][1] = r2;
            blo[np * 2 + 1][0] = r1; blo[np * 2 + 1][1] = r3;
        }

#pragma unroll
        for (int ns = 0; ns < 4; ns++) {
            mma16816(acc[ns], ahi[0], ahi[1], ahi[2], ahi[3], bhi[ns][0], bhi[ns][1]);
            mma16816(acc[ns], ahi[0], ahi[1], ahi[2], ahi[3], blo[ns][0], blo[ns][1]);
            mma16816(acc[ns], alo[0], alo[1], alo[2], alo[3], bhi[ns][0], bhi[ns][1]);
        }
        __syncthreads();
    }

    int gid = lane >> 2, tig = lane & 3;
#pragma unroll
    for (int ns = 0; ns < 4; ns++) {
        int gc = ns * 8 + tig * 2;
        float b0 = bias[gc], b1v = bias[gc + 1];
        int r0 = m0 + m_off + gid;
        int r1 = r0 + 8;
        if (r0 < N_NODES) {
            float2 o; o.x = acc[ns][0] + b0; o.y = acc[ns][1] + b1v;
            *(float2*)(g_z + (size_t)r0 * OUT_F + gc) = o;
        }
        if (r1 < N_NODES) {
            float2 o; o.x = acc[ns][2] + b0; o.y = acc[ns][3] + b1v;
            *(float2*)(g_z + (size_t)r1 * OUT_F + gc) = o;
        }
    }
}

// out[e] = dot(z[s], z[d]) over 32 dims. One warp per edge.
__global__ void decode_kernel(const int* __restrict__ eli,
                              float* __restrict__ out, int EL) {
    long long gt = (long long)blockIdx.x * blockDim.x + threadIdx.x;
    int w = (int)(gt >> 5);
    int lane = threadIdx.x & 31;
    if (w >= EL) return;
    int s = eli[w];
    int d = eli[EL + w];
    float v = g_z[(size_t)s * OUT_F + lane] * g_z[(size_t)d * OUT_F + lane];
#pragma unroll
    for (int o = 16; o > 0; o >>= 1) v += __shfl_down_sync(0xFFFFFFFFu, v, o);
    if (lane == 0) out[w] = v;
}

extern "C" void kernel_launch(void* const* d_in, const int* in_sizes, int n_in,
                              void* d_out, int out_size) {
    const float* x   = (const float*)d_in[0];
    const int*   ei  = (const int*)d_in[1];
    const int*   eli = (const int*)d_in[2];
    const float* W1l = (const float*)d_in[3];
    const float* b1  = (const float*)d_in[4];
    const float* W1r = (const float*)d_in[5];
    const float* W2l = (const float*)d_in[6];
    const float* b2  = (const float*)d_in[7];
    const float* W2r = (const float*)d_in[8];
    float* out = (float*)d_out;

    int E  = in_sizes[1] / 2;
    int EL = in_sizes[2] / 2;

    const int* src = ei;
    const int* dst = ei + E;

    const int T = 256;
    int ne_blk = (E + T - 1) / T;

    // g_deg is zero on entry (zeroed at module load; re-zeroed at the end of
    // every call below) -> hist can run first, putting gather1 at launch
    // index 3 for the ncu capture.
    hist_kernel<<<ne_blk, T>>>(dst, E);                                   // 0
    scan_single_kernel<<<1, 1024>>>();                                    // 1
    fill_adj_kernel<<<ne_blk, T>>>(src, dst, E);                          // 2
    gather1_kernel<<<(N_NODES * 32 + T - 1) / T, T>>>(x);                 // 3  <- profiled
    convert_x_kernel<<<(N_NODES * 32 + T - 1) / T, T>>>(x);               // 4
    convert_w1_kernel<<<(256 * 256 + T - 1) / T, T>>>(W1l, W1r);          // 5
    {
        dim3 grid((N_NODES + 127) / 128, 2);
        gemm1_mma_kernel<<<grid, 512>>>(b1);                              // 6
    }
    gather2_kernel<<<(N_NODES * 2 * 32 + T - 1) / T, T>>>();              // 7
    convert_w2_kernel<<<(512 * OUT_F + T - 1) / T, T>>>(W2l, W2r);        // 8
    gemm2_mma_kernel<<<(N_NODES + 127) / 128, 256>>>(b2);                 // 9
    {
        long long threads = (long long)EL * 32;
        decode_kernel<<<(int)((threads + T - 1) / T), T>>>(eli, out, EL); // 10
    }
    // restore the g_deg == 0 invariant for the next call
    zero_deg_kernel<<<(N_NODES + T - 1) / T, T>>>();                      // 11
}